// round 16
// baseline (speedup 1.0000x reference)
#include <cuda_runtime.h>
#include <cuda_bf16.h>

#define CCH 256
#define CMID 16
#define HWSZ 16384
#define NGRP 32

typedef unsigned long long ull;

// ---- device scratch (no allocations) ----
__device__ float g_dw[201326592];   // bf16 view: 6 dw planes; U at U_OFF
__device__ float g_q[4194304];      // [input][b][m][hw]  fp32
__device__ float g_k[4194304];
__device__ float g_fused[33554432]; // [b][c][hw] fp32
__device__ float g_psum[131072];
__device__ float2 g_stats[256];
__device__ uint4 g_wfrag[8192];     // Wv bf16 fragment-order [mt][kt][1024]

#define U_OFF 201326592

__device__ __forceinline__ unsigned pk2(float x, float y)
{
    __nv_bfloat162 h = __floats2bfloat162_rn(x, y);
    return *reinterpret_cast<unsigned*>(&h);
}

// ---- packed fp32 (f32x2) helpers ----
__device__ __forceinline__ ull pkf2(float x, float y)
{ ull r; asm("mov.b64 %0, {%1,%2};" : "=l"(r) : "f"(x), "f"(y)); return r; }
__device__ __forceinline__ void unpkf2(ull v, float& x, float& y)
{ asm("mov.b64 {%0,%1}, %2;" : "=f"(x), "=f"(y) : "l"(v)); }
__device__ __forceinline__ void fma2(ull& d, ull a, ull b)
{ asm("fma.rn.f32x2 %0, %1, %2, %0;" : "+l"(d) : "l"(a), "l"(b)); }

__device__ __forceinline__ void mma_bf16(float d[4], const unsigned a[4], const unsigned bb[2])
{
    asm volatile("mma.sync.aligned.m16n8k16.row.col.f32.bf16.bf16.f32 "
        "{%0,%1,%2,%3},{%4,%5,%6,%7},{%8,%9},{%0,%1,%2,%3};"
        : "+f"(d[0]),"+f"(d[1]),"+f"(d[2]),"+f"(d[3])
        : "r"(a[0]),"r"(a[1]),"r"(a[2]),"r"(a[3]),"r"(bb[0]),"r"(bb[1]));
}

__device__ __forceinline__ void cpa16(unsigned saddr, const void* gaddr)
{ asm volatile("cp.async.ca.shared.global [%0], [%1], 16;" :: "r"(saddr), "l"(gaddr) : "memory"); }

// ---- K0: one-time Wv -> bf16 fragment-order prep ----
__global__ __launch_bounds__(256) void wfrag_kernel(const float* __restrict__ Wv)
{
    int idx = blockIdx.x*256 + threadIdx.x;
    int mt = idx >> 12, kt = (idx >> 10) & 3, e = idx & 1023;
    int le = e & 31, fr = e >> 5;
    int ks = fr >> 3, wM = (fr >> 2) & 1, i = fr & 3;
    int m = mt*128 + wM*64 + i*16 + (le>>2);
    int k = kt*64 + ks*16 + 2*(le&3);
    const float* wp = &Wv[(size_t)m*256 + k];
    g_wfrag[idx] = make_uint4(pk2(wp[0],       wp[1]),
                              pk2(wp[8*256],   wp[8*256+1]),
                              pk2(wp[8],       wp[9]),
                              pk2(wp[8*256+8], wp[8*256+9]));
}

// ---- K1: fused depthwise 3x3 (q,k,v), f32x2 accumulation, bf16 outputs ----
__global__ __launch_bounds__(256) void dw_kernel(
    const float* __restrict__ img, const float* __restrict__ mask,
    const float* __restrict__ qw, const float* __restrict__ qb,
    const float* __restrict__ kw, const float* __restrict__ kb,
    const float* __restrict__ vw, const float* __restrict__ vb)
{
    int bid = blockIdx.x;
    int band = bid & 15;
    int bc = (bid >> 4) & 2047;
    int input = bid >> 15;
    int c = bc & 255;
    const float* src = (input ? mask : img) + (size_t)bc * HWSZ;

    __shared__ float s[10 * 132];
    int t = threadIdx.x;
    int y0 = band * 8;
    for (int i = t; i < 10 * 130; i += 256) {
        int r = i / 130, cc = i - r * 130;
        int gy = y0 - 1 + r, gx = cc - 1;
        float v = 0.f;
        if ((unsigned)gy < 128u && (unsigned)gx < 128u) v = src[gy * 128 + gx];
        s[r * 132 + cc] = v;
    }
    ull wq2[9], wk2[9], wv2[9];
#pragma unroll
    for (int j = 0; j < 9; j++) {
        float a = qw[c*9+j], b = kw[c*9+j], d = vw[c*9+j];
        wq2[j] = pkf2(a,a); wk2[j] = pkf2(b,b); wv2[j] = pkf2(d,d);
    }
    float bq = qb[c], bk = kb[c], bv = vb[c];
    __syncthreads();

    int x = t & 127, quad = t >> 7;
    ull aq2[2], ak2[2], av2[2];
    aq2[0]=aq2[1]=pkf2(bq,bq); ak2[0]=ak2[1]=pkf2(bk,bk); av2[0]=av2[1]=pkf2(bv,bv);
#pragma unroll
    for (int dx = 0; dx < 3; dx++) {
        float col[6];
#pragma unroll
        for (int rr = 0; rr < 6; rr++) col[rr] = s[(quad*4+rr)*132 + x + dx];
#pragma unroll
        for (int dy = 0; dy < 3; dy++) {
            ull m0 = pkf2(col[dy],   col[dy+1]);
            ull m1 = pkf2(col[dy+2], col[dy+3]);
            int j = dy*3 + dx;
            fma2(aq2[0], wq2[j], m0); fma2(aq2[1], wq2[j], m1);
            fma2(ak2[0], wk2[j], m0); fma2(ak2[1], wk2[j], m1);
            fma2(av2[0], wv2[j], m0); fma2(av2[1], wv2[j], m1);
        }
    }
    float aq[4], ak[4], av[4];
    unpkf2(aq2[0], aq[0], aq[1]); unpkf2(aq2[1], aq[2], aq[3]);
    unpkf2(ak2[0], ak[0], ak[1]); unpkf2(ak2[1], ak[2], ak[3]);
    unpkf2(av2[0], av[0], av[1]); unpkf2(av2[1], av[2], av[3]);

    __nv_bfloat16* gdw = (__nv_bfloat16*)g_dw;
    __nv_bfloat16* dq = gdw + ((size_t)(0 + input)*2048 + bc)*(size_t)HWSZ;
    __nv_bfloat16* dk = gdw + ((size_t)(2 + input)*2048 + bc)*(size_t)HWSZ;
    __nv_bfloat16* dv = gdw + ((size_t)(4 + input)*2048 + bc)*(size_t)HWSZ;
#pragma unroll
    for (int r = 0; r < 4; r++) {
        int y = y0 + quad*4 + r;
        dq[y*128 + x] = __float2bfloat16(aq[r]);
        dk[y*128 + x] = __float2bfloat16(ak[r]);
        dv[y*128 + x] = __float2bfloat16(av[r]);
    }
}

// ---- K2: q/k pointwise, f32x2 over m-pairs, bf16 inputs ----
__global__ __launch_bounds__(256) void pwqk_kernel(
    const float* __restrict__ qpw_w, const float* __restrict__ qpw_b,
    const float* __restrict__ kpw_w, const float* __restrict__ kpw_b)
{
    int which = blockIdx.y;
    int input = which & 1, proj = which >> 1;
    const float* Wp = proj ? kpw_w : qpw_w;
    const float* bp = proj ? kpw_b : qpw_b;
    const __nv_bfloat16* dwb = ((const __nv_bfloat16*)g_dw)
                               + (size_t)(proj*2 + input)*2048*(size_t)HWSZ;
    float* outb = (proj ? g_k : g_q) + (size_t)input*8*CMID*HWSZ;

    __shared__ ull ws2[8*256];
    __shared__ float bs[CMID];
    int t = threadIdx.x;
    for (int i = t; i < 2048; i += 256) {
        int mp = i >> 8, c = i & 255;
        ws2[i] = pkf2(Wp[(2*mp)*256 + c], Wp[(2*mp+1)*256 + c]);
    }
    if (t < CMID) bs[t] = bp[t];
    __syncthreads();

    int n = blockIdx.x*256 + t;
    int b = n >> 14, hw = n & 16383;
    const __nv_bfloat16* xp = dwb + ((size_t)b*CCH)*HWSZ + hw;
    ull acc2[8];
#pragma unroll
    for (int mp = 0; mp < 8; mp++) acc2[mp] = pkf2(bs[2*mp], bs[2*mp+1]);
#pragma unroll 4
    for (int c4 = 0; c4 < 64; c4++) {
        float x0 = __bfloat162float(xp[(size_t)(4*c4+0)*HWSZ]);
        float x1 = __bfloat162float(xp[(size_t)(4*c4+1)*HWSZ]);
        float x2 = __bfloat162float(xp[(size_t)(4*c4+2)*HWSZ]);
        float x3 = __bfloat162float(xp[(size_t)(4*c4+3)*HWSZ]);
        ull X0 = pkf2(x0,x0), X1 = pkf2(x1,x1), X2 = pkf2(x2,x2), X3 = pkf2(x3,x3);
#pragma unroll
        for (int mp = 0; mp < 8; mp++) {
            ulonglong2 wa = *(const ulonglong2*)&ws2[mp*256 + 4*c4];
            ulonglong2 wb = *(const ulonglong2*)&ws2[mp*256 + 4*c4 + 2];
            fma2(acc2[mp], wa.x, X0); fma2(acc2[mp], wa.y, X1);
            fma2(acc2[mp], wb.x, X2); fma2(acc2[mp], wb.y, X3);
        }
    }
    float* op = outb + ((size_t)b*CMID)*HWSZ + hw;
#pragma unroll
    for (int mp = 0; mp < 8; mp++) {
        float a0, a1;
        unpkf2(acc2[mp], a0, a1);
        op[(size_t)(2*mp)*HWSZ]   = a0;
        op[(size_t)(2*mp+1)*HWSZ] = a1;
    }
}

// ---- K3 helpers (probs stride 66; V in bf16) ----
#define STR 66

__device__ __forceinline__ void qk_gemm(const float* sQ, const float* sK, float* sSt, int t)
{
    int tx = t & 15, ty = t >> 4;
    int q0 = tx*4, p0 = ty*4;
    ull a2[4][2];
#pragma unroll
    for (int i=0;i<4;i++) { a2[i][0]=0ull; a2[i][1]=0ull; }
#pragma unroll
    for (int c = 0; c < 16; c++) {
        float4 kk = *(const float4*)&sK[c*64 + q0];
        ulonglong2 qq = *(const ulonglong2*)&sQ[c*64 + p0];
        ull ks0 = pkf2(kk.x,kk.x), ks1 = pkf2(kk.y,kk.y);
        ull ks2 = pkf2(kk.z,kk.z), ks3 = pkf2(kk.w,kk.w);
        fma2(a2[0][0], ks0, qq.x); fma2(a2[0][1], ks0, qq.y);
        fma2(a2[1][0], ks1, qq.x); fma2(a2[1][1], ks1, qq.y);
        fma2(a2[2][0], ks2, qq.x); fma2(a2[2][1], ks2, qq.y);
        fma2(a2[3][0], ks3, qq.x); fma2(a2[3][1], ks3, qq.y);
    }
#pragma unroll
    for (int i=0;i<4;i++) {
        float v0,v1,v2,v3;
        unpkf2(a2[i][0], v0, v1);
        unpkf2(a2[i][1], v2, v3);
        float* row = &sSt[(q0+i)*STR + p0];
        row[0] = 0.25f*v0; row[1] = 0.25f*v1; row[2] = 0.25f*v2; row[3] = 0.25f*v3;
    }
}

__device__ __forceinline__ void softmax_all(float* sSt, int t, float scale)
{
    int p = t >> 2, qt = t & 3;
    float* col = sSt + p;
    float mx = -1e30f;
#pragma unroll
    for (int i = 0; i < 16; i++) mx = fmaxf(mx, col[(qt*16 + i)*STR]);
    mx = fmaxf(mx, __shfl_xor_sync(0xffffffffu, mx, 1));
    mx = fmaxf(mx, __shfl_xor_sync(0xffffffffu, mx, 2));
    float e[16], sum = 0.f;
#pragma unroll
    for (int i = 0; i < 16; i++) {
        e[i] = __expf(col[(qt*16 + i)*STR] - mx);
        sum += e[i];
    }
    sum += __shfl_xor_sync(0xffffffffu, sum, 1);
    sum += __shfl_xor_sync(0xffffffffu, sum, 2);
    float inv = scale / sum;
#pragma unroll
    for (int i = 0; i < 16; i++)
        col[(qt*16 + i)*STR] = e[i]*inv;
}

// V in bf16 [q][256] with 16B-chunk XOR swizzle: chunk' = chunk ^ ((q>>3)&7)
__device__ __forceinline__ void t_accum(ull acc2[8][4], const __nv_bfloat16* sVtb,
                                        const float* sSt, int cg, int p0)
{
#pragma unroll 2
    for (int q = 0; q < 64; q++) {
        int ch = cg ^ ((q >> 3) & 7);
        uint4 vr = *(const uint4*)&sVtb[q*256 + ch*8];
        ull u0 = *(const ull*)&sSt[q*STR + p0];
        ull u1 = *(const ull*)&sSt[q*STR + p0 + 2];
        ull u2 = *(const ull*)&sSt[q*STR + p0 + 4];
        ull u3 = *(const ull*)&sSt[q*STR + p0 + 6];
        const __nv_bfloat162* hp = (const __nv_bfloat162*)&vr;
        float2 f0 = __bfloat1622float2(hp[0]);
        float2 f1 = __bfloat1622float2(hp[1]);
        float2 f2 = __bfloat1622float2(hp[2]);
        float2 f3 = __bfloat1622float2(hp[3]);
        float vv[8] = {f0.x,f0.y,f1.x,f1.y,f2.x,f2.y,f3.x,f3.y};
#pragma unroll
        for (int i=0;i<8;i++) {
            ull vs = pkf2(vv[i], vv[i]);
            fma2(acc2[i][0], vs, u0);
            fma2(acc2[i][1], vs, u1);
            fma2(acc2[i][2], vs, u2);
            fma2(acc2[i][3], vs, u3);
        }
    }
}

// smem (floats): sQ 0(1024) sK 1024(1024) St1 2048(4224) St2 6272(4224)
//                sVt bf16 10496(8192 fl) -> total 18688 fl = 74752 B (3 CTAs/SM)
#define ATTN_SMEM_FLOATS 18688

__global__ __launch_bounds__(256, 3) void attn_kernel(
    const float* __restrict__ alpha_p, const float* __restrict__ beta_p)
{
    extern __shared__ float sm[];
    float* sQ   = sm;
    float* sK   = sm + 1024;
    float* sSt1 = sm + 2048;
    float* sSt2 = sm + 6272;
    __nv_bfloat16* sVtb = (__nv_bfloat16*)(sm + 10496);

    int t = threadIdx.x;
    int bid = blockIdx.x;
    int b = bid >> 8, blkid = bid & 255;
    int by = blkid >> 4, bx = blkid & 15;
    float al = __ldg(alpha_p), be = __ldg(beta_p);
    int hw00 = by*8*128 + bx*8;
    const __nv_bfloat16* gdw = (const __nv_bfloat16*)g_dw;

    {
        const float* qs = g_q + (((size_t)8 + b)*CMID)*HWSZ;
        const float* ks = g_k + (((size_t)0 + b)*CMID)*HWSZ;
        for (int e = t; e < 1024; e += 256) {
            int m = e >> 6, p = e & 63;
            int hw = hw00 + ((p>>3)<<7) + (p&7);
            sQ[m*64+p] = qs[(size_t)m*HWSZ + hw];
            sK[m*64+p] = ks[(size_t)m*HWSZ + hw];
        }
    }
    __syncthreads();
    qk_gemm(sQ, sK, sSt1, t);
    __syncthreads();
    {
        const float* qs = g_q + (((size_t)0 + b)*CMID)*HWSZ;
        const float* ks = g_k + (((size_t)8 + b)*CMID)*HWSZ;
        float qr[4], kr[4];
#pragma unroll
        for (int s = 0; s < 4; s++) {
            int e = s*256 + t;
            int m = e >> 6, p = e & 63;
            int hw = hw00 + ((p>>3)<<7) + (p&7);
            qr[s] = qs[(size_t)m*HWSZ + hw];
            kr[s] = ks[(size_t)m*HWSZ + hw];
        }
        softmax_all(sSt1, t, al);
#pragma unroll
        for (int s = 0; s < 4; s++) {
            int e = s*256 + t;
            int m = e >> 6, p = e & 63;
            sQ[m*64+p] = qr[s]; sK[m*64+p] = kr[s];
        }
    }
    __syncthreads();
    qk_gemm(sQ, sK, sSt2, t);
    __syncthreads();
    {   // fill V1 (raw bf16, transposed [q][c], chunk-swizzled)
        const __nv_bfloat16* vs = gdw + (((size_t)4*8 + b)*CCH)*(size_t)HWSZ;
#pragma unroll
        for (int s = 0; s < 8; s++) {
            int e = s*256 + t;
            int c = e >> 3, pg = e & 7;
            uint4 raw = *(const uint4*)&vs[(size_t)c*HWSZ + hw00 + pg*128];
            const __nv_bfloat16* hv = (const __nv_bfloat16*)&raw;
            int ch = (c >> 3) ^ pg;
            int base = ch*8 + (c & 7);
#pragma unroll
            for (int i = 0; i < 8; i++)
                sVtb[(pg*8 + i)*256 + base] = hv[i];
        }
        softmax_all(sSt2, t, be);
    }
    __syncthreads();

    int pg = t & 7, cg = t >> 3;
    int c0 = cg*8, p0 = pg*8;
    ull acc2[8][4];
#pragma unroll
    for (int i=0;i<8;i++)
#pragma unroll
        for (int jp=0;jp<4;jp++) acc2[i][jp]=0ull;

    t_accum(acc2, sVtb, sSt1, cg, p0);
    __syncthreads();
    {   // fill V2
        const __nv_bfloat16* vs = gdw + (((size_t)5*8 + b)*CCH)*(size_t)HWSZ;
#pragma unroll
        for (int s = 0; s < 8; s++) {
            int e = s*256 + t;
            int c = e >> 3, pgv = e & 7;
            uint4 raw = *(const uint4*)&vs[(size_t)c*HWSZ + hw00 + pgv*128];
            const __nv_bfloat16* hv = (const __nv_bfloat16*)&raw;
            int ch = (c >> 3) ^ pgv;
            int base = ch*8 + (c & 7);
#pragma unroll
            for (int i = 0; i < 8; i++)
                sVtb[(pgv*8 + i)*256 + base] = hv[i];
        }
    }
    __syncthreads();
    t_accum(acc2, sVtb, sSt2, cg, p0);

    float acc[8][8];
#pragma unroll
    for (int i=0;i<8;i++)
#pragma unroll
        for (int jp=0;jp<4;jp++)
            unpkf2(acc2[i][jp], acc[i][2*jp], acc[i][2*jp+1]);

    __nv_bfloat16* Ub = ((__nv_bfloat16*)g_dw) + U_OFF;
    size_t ub = ((size_t)b*HWSZ + (size_t)hw00 + (size_t)pg*128)*256 + c0;
#pragma unroll
    for (int j = 0; j < 8; j++) {
        uint4 pkt = make_uint4(pk2(acc[0][j], acc[1][j]), pk2(acc[2][j], acc[3][j]),
                               pk2(acc[4][j], acc[5][j]), pk2(acc[6][j], acc[7][j]));
        *(uint4*)&Ub[ub + (size_t)j*256] = pkt;
    }
}

// ---- K4: bf16 GEMM, cp.async double-buffered fills, 2 CTAs/SM ----
#define GEMM_SMEM_BYTES 69632

__global__ __launch_bounds__(256, 2) void gemm_kernel(
    const float* __restrict__ bvp,
    const float* __restrict__ img, const float* __restrict__ mask,
    const float* __restrict__ alpha_p, const float* __restrict__ beta_p)
{
    extern __shared__ unsigned sg[];
    uint4* sAf = (uint4*)sg;                          // [2][1024]
    __nv_bfloat16* sB = (__nv_bfloat16*)(sg + 8192);  // [2][128*72]
    const __nv_bfloat16* Ub = ((const __nv_bfloat16*)g_dw) + U_OFF;

    const int t = threadIdx.x, lane = t & 31, warp = t >> 5;
    const int warpM = warp >> 2, warpN = warp & 3;
    const int hwt = blockIdx.x, mt = blockIdx.y, b = blockIdx.z;
    const int n0 = hwt * 128;

    unsigned sA_base = (unsigned)__cvta_generic_to_shared(sAf);
    unsigned sB_base = (unsigned)__cvta_generic_to_shared(sB);

    float d[4][4][4];
#pragma unroll
    for (int i=0;i<4;i++)
#pragma unroll
        for (int j=0;j<4;j++)
#pragma unroll
            for (int e=0;e<4;e++) d[i][j][e]=0.f;

    {
#pragma unroll
        for (int s = 0; s < 4; s++) {
            int e = s*256 + t;
            cpa16(sA_base + e*16, &g_wfrag[(mt*4 + 0)*1024 + e]);
        }
#pragma unroll
        for (int s = 0; s < 4; s++) {
            int e = s*256 + t;
            int n = e >> 3, kq = e & 7;
            cpa16(sB_base + (n*72 + kq*8)*2,
                  &Ub[((size_t)b*HWSZ + n0 + n)*256 + kq*8]);
        }
        asm volatile("cp.async.commit_group;" ::: "memory");
    }

    for (int kt = 0; kt < 4; kt++) {
        if (kt < 3) {
            int kn = kt + 1, buf = kn & 1;
            int kc = kn*64;
#pragma unroll
            for (int s = 0; s < 4; s++) {
                int e = s*256 + t;
                cpa16(sA_base + (buf*1024 + e)*16, &g_wfrag[(mt*4 + kn)*1024 + e]);
            }
#pragma unroll
            for (int s = 0; s < 4; s++) {
                int e = s*256 + t;
                int n = e >> 3, kq = e & 7;
                cpa16(sB_base + (buf*9216 + n*72 + kq*8)*2,
                      &Ub[((size_t)b*HWSZ + n0 + n)*256 + kc + kq*8]);
            }
            asm volatile("cp.async.commit_group;" ::: "memory");
            asm volatile("cp.async.wait_group 1;" ::: "memory");
        } else {
            asm volatile("cp.async.wait_group 0;" ::: "memory");
        }
        __syncthreads();

        const uint4* A = sAf + (kt & 1)*1024;
        const __nv_bfloat16* Bs = sB + (kt & 1)*9216;
#pragma unroll
        for (int ks = 0; ks < 4; ks++) {
            int kl = ks*16 + 2*(lane & 3);
            uint4 av[4];
#pragma unroll
            for (int i = 0; i < 4; i++)
                av[i] = A[((ks*2 + warpM)*4 + i)*32 + lane];
            unsigned bb[4][2];
#pragma unroll
            for (int j = 0; j < 4; j++) {
                int n = warpN*32 + j*8 + (lane >> 2);
                bb[j][0] = *(const unsigned*)&Bs[n*72 + kl];
                bb[j][1] = *(const unsigned*)&Bs[n*72 + kl + 8];
            }
#pragma unroll
            for (int i = 0; i < 4; i++) {
                unsigned a[4] = {av[i].x, av[i].y, av[i].z, av[i].w};
#pragma unroll
                for (int j = 0; j < 4; j++) mma_bf16(d[i][j], a, bb[j]);
            }
        }
        __syncthreads();
    }

    float* red = (float*)sg;
    float ab = __ldg(alpha_p) + __ldg(beta_p);
    int r = lane >> 2, cc = (lane & 3)*2;
    int slot = warpN*4 + (lane & 3);
#pragma unroll
    for (int i = 0; i < 4; i++) {
#pragma unroll
        for (int half = 0; half < 2; half++) {
            int ro = warpM*64 + i*16 + r + half*8;
            int o = mt*128 + ro;
            float bias = ab * __ldg(&bvp[o]);
            float s = 0.f, q = 0.f;
#pragma unroll
            for (int j = 0; j < 4; j++) {
                int nl = warpN*32 + j*8 + cc;
                size_t g = ((size_t)(b*256 + o) << 14) + n0 + nl;
                float2 iv = *(const float2*)&img[g];
                float2 mv = *(const float2*)&mask[g];
                float v0 = d[i][j][half*2+0] + bias + iv.x + mv.x;
                float v1 = d[i][j][half*2+1] + bias + iv.y + mv.y;
                *(float2*)&g_fused[g] = make_float2(v0, v1);
                s += v0 + v1; q += v0*v0 + v1*v1;
            }
            red[ro*16 + slot]        = s;
            red[2048 + ro*16 + slot] = q;
        }
    }
    __syncthreads();
    if (t < 128) {
        float s = 0.f, q = 0.f;
#pragma unroll
        for (int k = 0; k < 16; k++) { s += red[t*16+k]; q += red[2048 + t*16+k]; }
        red[4096 + t] = s; red[4224 + t] = q;
    }
    __syncthreads();
    if (t < 16) {
        float s = 0.f, q = 0.f;
#pragma unroll
        for (int k = 0; k < 8; k++) { s += red[4096 + t*8+k]; q += red[4224 + t*8+k]; }
        int g = mt*16 + t;
        int idx = ((b*32 + g)*128 + hwt)*2;
        g_psum[idx] = s; g_psum[idx+1] = q;
    }
}

// ---- K5: reduce GN partials ----
__global__ __launch_bounds__(128) void stats_kernel()
{
    int bg = blockIdx.x, t = threadIdx.x;
    float2 v = ((const float2*)g_psum)[bg*128 + t];
    float s = v.x, q = v.y;
#pragma unroll
    for (int o = 16; o; o >>= 1) {
        s += __shfl_xor_sync(0xffffffffu, s, o);
        q += __shfl_xor_sync(0xffffffffu, q, o);
    }
    __shared__ float ss[4], qs[4];
    if ((t & 31) == 0) { ss[t>>5] = s; qs[t>>5] = q; }
    __syncthreads();
    if (t == 0) {
        for (int w = 1; w < 4; w++) { s += ss[w]; q += qs[w]; }
        float inv = 1.f / 131072.f;
        float mu = s * inv;
        float var = q * inv - mu*mu;
        g_stats[bg] = make_float2(mu, rsqrtf(var + 1e-5f));
    }
}

// ---- K6: normalize ----
__global__ __launch_bounds__(1024) void norm_kernel(
    float* __restrict__ out, const float* __restrict__ gamma, const float* __restrict__ beta)
{
    int i4 = blockIdx.x*1024 + threadIdx.x;
    size_t e = (size_t)i4 << 2;
    int b = (int)(e >> 22), c = (int)(e >> 14) & 255;
    float2 st = g_stats[b*32 + (c >> 3)];
    float gsc = gamma[c] * st.y;
    float bsh = beta[c] - st.x * gsc;
    float4 f = *(const float4*)&g_fused[e];
    float4 r;
    r.x = f.x*gsc + bsh; r.y = f.y*gsc + bsh;
    r.z = f.z*gsc + bsh; r.w = f.w*gsc + bsh;
    *(float4*)&out[e] = r;
}

extern "C" void kernel_launch(void* const* d_in, const int* in_sizes, int n_in,
                              void* d_out, int out_size)
{
    const float* img    = (const float*)d_in[0];
    const float* mask   = (const float*)d_in[1];
    const float* qdw_w  = (const float*)d_in[2];
    const float* qdw_b  = (const float*)d_in[3];
    const float* kdw_w  = (const float*)d_in[4];
    const float* kdw_b  = (const float*)d_in[5];
    const float* vdw_w  = (const float*)d_in[6];
    const float* vdw_b  = (const float*)d_in[7];
    const float* qpw_w  = (const float*)d_in[8];
    const float* qpw_b  = (const float*)d_in[9];
    const float* kpw_w  = (const float*)d_in[10];
    const float* kpw_b  = (const float*)d_in[11];
    const float* vpw_w  = (const float*)d_in[12];
    const float* vpw_b  = (const float*)d_in[13];
    const float* alpha  = (const float*)d_in[14];
    const float* beta   = (const float*)d_in[15];
    const float* gn_w   = (const float*)d_in[16];
    const float* gn_b   = (const float*)d_in[17];

    cudaFuncSetAttribute(attn_kernel, cudaFuncAttributeMaxDynamicSharedMemorySize,
                         ATTN_SMEM_FLOATS * 4);
    cudaFuncSetAttribute(gemm_kernel, cudaFuncAttributeMaxDynamicSharedMemorySize,
                         GEMM_SMEM_BYTES);

    wfrag_kernel<<<32, 256>>>(vpw_w);
    dw_kernel<<<65536, 256>>>(img, mask, qdw_w, qdw_b, kdw_w, kdw_b, vdw_w, vdw_b);
    dim3 g2(512, 4);
    pwqk_kernel<<<g2, 256>>>(qpw_w, qpw_b, kpw_w, kpw_b);
    attn_kernel<<<2048, 256, ATTN_SMEM_FLOATS * 4>>>(alpha, beta);
    dim3 g4(128, 2, 8);
    gemm_kernel<<<g4, 256, GEMM_SMEM_BYTES>>>(vpw_b, img, mask, alpha, beta);
    stats_kernel<<<256, 128>>>();
    norm_kernel<<<8192, 1024>>>((float*)d_out, gn_w, gn_b);
}

// round 17
// speedup vs baseline: 2.0750x; 2.0750x over previous
#include <cuda_runtime.h>
#include <cuda_bf16.h>

#define CCH 256
#define CMID 16
#define HWSZ 16384
#define NGRP 32

typedef unsigned long long ull;

// ---- device scratch (no allocations) ----
__device__ float g_dw[201326592];   // bf16 view: 6 dw planes; U at U_OFF
__device__ float g_q[4194304];      // [input][b][m][hw]  fp32
__device__ float g_k[4194304];
__device__ float g_fused[33554432]; // [b][c][hw] fp32
__device__ float g_psum[131072];
__device__ float2 g_stats[256];
__device__ uint4 g_wfrag[8192];     // Wv bf16 fragment-order [mt][kt][1024]

#define U_OFF 201326592

__device__ __forceinline__ unsigned pk2(float x, float y)
{
    __nv_bfloat162 h = __floats2bfloat162_rn(x, y);
    return *reinterpret_cast<unsigned*>(&h);
}

// ---- packed fp32 (f32x2) helpers ----
__device__ __forceinline__ ull pkf2(float x, float y)
{ ull r; asm("mov.b64 %0, {%1,%2};" : "=l"(r) : "f"(x), "f"(y)); return r; }
__device__ __forceinline__ void unpkf2(ull v, float& x, float& y)
{ asm("mov.b64 {%0,%1}, %2;" : "=f"(x), "=f"(y) : "l"(v)); }
__device__ __forceinline__ void fma2(ull& d, ull a, ull b)
{ asm("fma.rn.f32x2 %0, %1, %2, %0;" : "+l"(d) : "l"(a), "l"(b)); }

__device__ __forceinline__ void mma_bf16(float d[4], const unsigned a[4], const unsigned bb[2])
{
    asm volatile("mma.sync.aligned.m16n8k16.row.col.f32.bf16.bf16.f32 "
        "{%0,%1,%2,%3},{%4,%5,%6,%7},{%8,%9},{%0,%1,%2,%3};"
        : "+f"(d[0]),"+f"(d[1]),"+f"(d[2]),"+f"(d[3])
        : "r"(a[0]),"r"(a[1]),"r"(a[2]),"r"(a[3]),"r"(bb[0]),"r"(bb[1]));
}

__device__ __forceinline__ void cpa16(unsigned saddr, const void* gaddr)
{ asm volatile("cp.async.ca.shared.global [%0], [%1], 16;" :: "r"(saddr), "l"(gaddr) : "memory"); }

// ---- K0: one-time Wv -> bf16 fragment-order prep ----
__global__ __launch_bounds__(256) void wfrag_kernel(const float* __restrict__ Wv)
{
    int idx = blockIdx.x*256 + threadIdx.x;
    int mt = idx >> 12, kt = (idx >> 10) & 3, e = idx & 1023;
    int le = e & 31, fr = e >> 5;
    int ks = fr >> 3, wM = (fr >> 2) & 1, i = fr & 3;
    int m = mt*128 + wM*64 + i*16 + (le>>2);
    int k = kt*64 + ks*16 + 2*(le&3);
    const float* wp = &Wv[(size_t)m*256 + k];
    g_wfrag[idx] = make_uint4(pk2(wp[0],       wp[1]),
                              pk2(wp[8*256],   wp[8*256+1]),
                              pk2(wp[8],       wp[9]),
                              pk2(wp[8*256+8], wp[8*256+9]));
}

// ---- K1: fused depthwise 3x3 (q,k,v), f32x2 accumulation, bf16 outputs ----
__global__ __launch_bounds__(256) void dw_kernel(
    const float* __restrict__ img, const float* __restrict__ mask,
    const float* __restrict__ qw, const float* __restrict__ qb,
    const float* __restrict__ kw, const float* __restrict__ kb,
    const float* __restrict__ vw, const float* __restrict__ vb)
{
    int bid = blockIdx.x;
    int band = bid & 15;
    int bc = (bid >> 4) & 2047;
    int input = bid >> 15;
    int c = bc & 255;
    const float* src = (input ? mask : img) + (size_t)bc * HWSZ;

    __shared__ float s[10 * 132];
    int t = threadIdx.x;
    int y0 = band * 8;
    for (int i = t; i < 10 * 130; i += 256) {
        int r = i / 130, cc = i - r * 130;
        int gy = y0 - 1 + r, gx = cc - 1;
        float v = 0.f;
        if ((unsigned)gy < 128u && (unsigned)gx < 128u) v = src[gy * 128 + gx];
        s[r * 132 + cc] = v;
    }
    ull wq2[9], wk2[9], wv2[9];
#pragma unroll
    for (int j = 0; j < 9; j++) {
        float a = qw[c*9+j], b = kw[c*9+j], d = vw[c*9+j];
        wq2[j] = pkf2(a,a); wk2[j] = pkf2(b,b); wv2[j] = pkf2(d,d);
    }
    float bq = qb[c], bk = kb[c], bv = vb[c];
    __syncthreads();

    int x = t & 127, quad = t >> 7;
    ull aq2[2], ak2[2], av2[2];
    aq2[0]=aq2[1]=pkf2(bq,bq); ak2[0]=ak2[1]=pkf2(bk,bk); av2[0]=av2[1]=pkf2(bv,bv);
#pragma unroll
    for (int dx = 0; dx < 3; dx++) {
        float col[6];
#pragma unroll
        for (int rr = 0; rr < 6; rr++) col[rr] = s[(quad*4+rr)*132 + x + dx];
#pragma unroll
        for (int dy = 0; dy < 3; dy++) {
            ull m0 = pkf2(col[dy],   col[dy+1]);
            ull m1 = pkf2(col[dy+2], col[dy+3]);
            int j = dy*3 + dx;
            fma2(aq2[0], wq2[j], m0); fma2(aq2[1], wq2[j], m1);
            fma2(ak2[0], wk2[j], m0); fma2(ak2[1], wk2[j], m1);
            fma2(av2[0], wv2[j], m0); fma2(av2[1], wv2[j], m1);
        }
    }
    float aq[4], ak[4], av[4];
    unpkf2(aq2[0], aq[0], aq[1]); unpkf2(aq2[1], aq[2], aq[3]);
    unpkf2(ak2[0], ak[0], ak[1]); unpkf2(ak2[1], ak[2], ak[3]);
    unpkf2(av2[0], av[0], av[1]); unpkf2(av2[1], av[2], av[3]);

    __nv_bfloat16* gdw = (__nv_bfloat16*)g_dw;
    __nv_bfloat16* dq = gdw + ((size_t)(0 + input)*2048 + bc)*(size_t)HWSZ;
    __nv_bfloat16* dk = gdw + ((size_t)(2 + input)*2048 + bc)*(size_t)HWSZ;
    __nv_bfloat16* dv = gdw + ((size_t)(4 + input)*2048 + bc)*(size_t)HWSZ;
#pragma unroll
    for (int r = 0; r < 4; r++) {
        int y = y0 + quad*4 + r;
        dq[y*128 + x] = __float2bfloat16(aq[r]);
        dk[y*128 + x] = __float2bfloat16(ak[r]);
        dv[y*128 + x] = __float2bfloat16(av[r]);
    }
}

// ---- K2: q/k pointwise, pixel-pair f32x2, bf16 inputs ----
__global__ __launch_bounds__(256) void pwqk_kernel(
    const float* __restrict__ qpw_w, const float* __restrict__ qpw_b,
    const float* __restrict__ kpw_w, const float* __restrict__ kpw_b)
{
    int which = blockIdx.y;
    int input = which & 1, proj = which >> 1;
    const float* Wp = proj ? kpw_w : qpw_w;
    const float* bp = proj ? kpw_b : qpw_b;
    const __nv_bfloat16* dwb = ((const __nv_bfloat16*)g_dw)
                               + (size_t)(proj*2 + input)*2048*(size_t)HWSZ;
    float* outb = (proj ? g_k : g_q) + (size_t)input*8*CMID*HWSZ;

    __shared__ ull ws2[16*256];   // [m][c] : (w, w) broadcast pairs (32 KB)
    __shared__ float bs[CMID];
    int t = threadIdx.x;
    for (int i = t; i < 4096; i += 256) {
        float w = Wp[i];
        ws2[i] = pkf2(w, w);
    }
    if (t < CMID) bs[t] = bp[t];
    __syncthreads();

    int n = blockIdx.x*256 + t;          // pixel-pair index
    int b = n >> 13, hw = (n & 8191) * 2;
    const __nv_bfloat16* xp = dwb + ((size_t)b*CCH)*HWSZ + hw;
    ull acc2[16];                        // lanes = (px0, px1)
#pragma unroll
    for (int m = 0; m < 16; m++) acc2[m] = pkf2(bs[m], bs[m]);
#pragma unroll 4
    for (int c2 = 0; c2 < 128; c2++) {
        __nv_bfloat162 h0 = *(const __nv_bfloat162*)&xp[(size_t)(2*c2+0)*HWSZ];
        __nv_bfloat162 h1 = *(const __nv_bfloat162*)&xp[(size_t)(2*c2+1)*HWSZ];
        float2 f0 = __bfloat1622float2(h0);
        float2 f1 = __bfloat1622float2(h1);
        ull X0 = pkf2(f0.x, f0.y), X1 = pkf2(f1.x, f1.y);
#pragma unroll
        for (int m = 0; m < 16; m++) {
            ulonglong2 w = *(const ulonglong2*)&ws2[m*256 + 2*c2];
            fma2(acc2[m], w.x, X0);
            fma2(acc2[m], w.y, X1);
        }
    }
    float* op = outb + ((size_t)b*CMID)*HWSZ + hw;
#pragma unroll
    for (int m = 0; m < 16; m++) {
        float a0, a1;
        unpkf2(acc2[m], a0, a1);
        *(float2*)&op[(size_t)m*HWSZ] = make_float2(a0, a1);
    }
}

// ---- K3 helpers (probs stride 66; V in bf16) ----
#define STR 66

__device__ __forceinline__ void qk_gemm(const float* sQ, const float* sK, float* sSt, int t)
{
    int tx = t & 15, ty = t >> 4;
    int q0 = tx*4, p0 = ty*4;
    ull a2[4][2];
#pragma unroll
    for (int i=0;i<4;i++) { a2[i][0]=0ull; a2[i][1]=0ull; }
#pragma unroll
    for (int c = 0; c < 16; c++) {
        float4 kk = *(const float4*)&sK[c*64 + q0];
        ulonglong2 qq = *(const ulonglong2*)&sQ[c*64 + p0];
        ull ks0 = pkf2(kk.x,kk.x), ks1 = pkf2(kk.y,kk.y);
        ull ks2 = pkf2(kk.z,kk.z), ks3 = pkf2(kk.w,kk.w);
        fma2(a2[0][0], ks0, qq.x); fma2(a2[0][1], ks0, qq.y);
        fma2(a2[1][0], ks1, qq.x); fma2(a2[1][1], ks1, qq.y);
        fma2(a2[2][0], ks2, qq.x); fma2(a2[2][1], ks2, qq.y);
        fma2(a2[3][0], ks3, qq.x); fma2(a2[3][1], ks3, qq.y);
    }
#pragma unroll
    for (int i=0;i<4;i++) {
        float v0,v1,v2,v3;
        unpkf2(a2[i][0], v0, v1);
        unpkf2(a2[i][1], v2, v3);
        float* row = &sSt[(q0+i)*STR + p0];
        row[0] = 0.25f*v0; row[1] = 0.25f*v1; row[2] = 0.25f*v2; row[3] = 0.25f*v3;
    }
}

__device__ __forceinline__ void softmax_all(float* sSt, int t, float scale)
{
    int p = t >> 2, qt = t & 3;
    float* col = sSt + p;
    float mx = -1e30f;
#pragma unroll
    for (int i = 0; i < 16; i++) mx = fmaxf(mx, col[(qt*16 + i)*STR]);
    mx = fmaxf(mx, __shfl_xor_sync(0xffffffffu, mx, 1));
    mx = fmaxf(mx, __shfl_xor_sync(0xffffffffu, mx, 2));
    float e[16], sum = 0.f;
#pragma unroll
    for (int i = 0; i < 16; i++) {
        e[i] = __expf(col[(qt*16 + i)*STR] - mx);
        sum += e[i];
    }
    sum += __shfl_xor_sync(0xffffffffu, sum, 1);
    sum += __shfl_xor_sync(0xffffffffu, sum, 2);
    float inv = scale / sum;
#pragma unroll
    for (int i = 0; i < 16; i++)
        col[(qt*16 + i)*STR] = e[i]*inv;
}

// V in bf16 [q][256] with 16B-chunk XOR swizzle: chunk' = chunk ^ ((q>>3)&7)
__device__ __forceinline__ void t_accum(ull acc2[8][4], const __nv_bfloat16* sVtb,
                                        const float* sSt, int cg, int p0)
{
#pragma unroll 2
    for (int q = 0; q < 64; q++) {
        int ch = cg ^ ((q >> 3) & 7);
        uint4 vr = *(const uint4*)&sVtb[q*256 + ch*8];
        ull u0 = *(const ull*)&sSt[q*STR + p0];
        ull u1 = *(const ull*)&sSt[q*STR + p0 + 2];
        ull u2 = *(const ull*)&sSt[q*STR + p0 + 4];
        ull u3 = *(const ull*)&sSt[q*STR + p0 + 6];
        const __nv_bfloat162* hp = (const __nv_bfloat162*)&vr;
        float2 f0 = __bfloat1622float2(hp[0]);
        float2 f1 = __bfloat1622float2(hp[1]);
        float2 f2 = __bfloat1622float2(hp[2]);
        float2 f3 = __bfloat1622float2(hp[3]);
        float vv[8] = {f0.x,f0.y,f1.x,f1.y,f2.x,f2.y,f3.x,f3.y};
#pragma unroll
        for (int i=0;i<8;i++) {
            ull vs = pkf2(vv[i], vv[i]);
            fma2(acc2[i][0], vs, u0);
            fma2(acc2[i][1], vs, u1);
            fma2(acc2[i][2], vs, u2);
            fma2(acc2[i][3], vs, u3);
        }
    }
}

// smem (floats): sQ 0(1024) sK 1024(1024) St1 2048(4224) St2 6272(4224)
//                sVt bf16 10496(8192 fl) -> total 18688 fl = 74752 B
#define ATTN_SMEM_FLOATS 18688

__global__ __launch_bounds__(256, 2) void attn_kernel(
    const float* __restrict__ alpha_p, const float* __restrict__ beta_p)
{
    extern __shared__ float sm[];
    float* sQ   = sm;
    float* sK   = sm + 1024;
    float* sSt1 = sm + 2048;
    float* sSt2 = sm + 6272;
    __nv_bfloat16* sVtb = (__nv_bfloat16*)(sm + 10496);

    int t = threadIdx.x;
    int bid = blockIdx.x;
    int b = bid >> 8, blkid = bid & 255;
    int by = blkid >> 4, bx = blkid & 15;
    float al = __ldg(alpha_p), be = __ldg(beta_p);
    int hw00 = by*8*128 + bx*8;
    const __nv_bfloat16* gdw = (const __nv_bfloat16*)g_dw;

    {
        const float* qs = g_q + (((size_t)8 + b)*CMID)*HWSZ;
        const float* ks = g_k + (((size_t)0 + b)*CMID)*HWSZ;
        for (int e = t; e < 1024; e += 256) {
            int m = e >> 6, p = e & 63;
            int hw = hw00 + ((p>>3)<<7) + (p&7);
            sQ[m*64+p] = qs[(size_t)m*HWSZ + hw];
            sK[m*64+p] = ks[(size_t)m*HWSZ + hw];
        }
    }
    __syncthreads();
    qk_gemm(sQ, sK, sSt1, t);
    __syncthreads();
    {
        const float* qs = g_q + (((size_t)0 + b)*CMID)*HWSZ;
        const float* ks = g_k + (((size_t)8 + b)*CMID)*HWSZ;
        float qr[4], kr[4];
#pragma unroll
        for (int s = 0; s < 4; s++) {
            int e = s*256 + t;
            int m = e >> 6, p = e & 63;
            int hw = hw00 + ((p>>3)<<7) + (p&7);
            qr[s] = qs[(size_t)m*HWSZ + hw];
            kr[s] = ks[(size_t)m*HWSZ + hw];
        }
        softmax_all(sSt1, t, al);
#pragma unroll
        for (int s = 0; s < 4; s++) {
            int e = s*256 + t;
            int m = e >> 6, p = e & 63;
            sQ[m*64+p] = qr[s]; sK[m*64+p] = kr[s];
        }
    }
    __syncthreads();
    qk_gemm(sQ, sK, sSt2, t);
    __syncthreads();
    {   // fill V1 (raw bf16, transposed [q][c], chunk-swizzled)
        const __nv_bfloat16* vs = gdw + (((size_t)4*8 + b)*CCH)*(size_t)HWSZ;
#pragma unroll
        for (int s = 0; s < 8; s++) {
            int e = s*256 + t;
            int c = e >> 3, pg = e & 7;
            uint4 raw = *(const uint4*)&vs[(size_t)c*HWSZ + hw00 + pg*128];
            const __nv_bfloat16* hv = (const __nv_bfloat16*)&raw;
            int ch = (c >> 3) ^ pg;
            int base = ch*8 + (c & 7);
#pragma unroll
            for (int i = 0; i < 8; i++)
                sVtb[(pg*8 + i)*256 + base] = hv[i];
        }
        softmax_all(sSt2, t, be);
    }
    __syncthreads();

    int pg = t & 7, cg = t >> 3;
    int c0 = cg*8, p0 = pg*8;
    ull acc2[8][4];
#pragma unroll
    for (int i=0;i<8;i++)
#pragma unroll
        for (int jp=0;jp<4;jp++) acc2[i][jp]=0ull;

    t_accum(acc2, sVtb, sSt1, cg, p0);
    __syncthreads();
    {   // fill V2
        const __nv_bfloat16* vs = gdw + (((size_t)5*8 + b)*CCH)*(size_t)HWSZ;
#pragma unroll
        for (int s = 0; s < 8; s++) {
            int e = s*256 + t;
            int c = e >> 3, pgv = e & 7;
            uint4 raw = *(const uint4*)&vs[(size_t)c*HWSZ + hw00 + pgv*128];
            const __nv_bfloat16* hv = (const __nv_bfloat16*)&raw;
            int ch = (c >> 3) ^ pgv;
            int base = ch*8 + (c & 7);
#pragma unroll
            for (int i = 0; i < 8; i++)
                sVtb[(pgv*8 + i)*256 + base] = hv[i];
        }
    }
    __syncthreads();
    t_accum(acc2, sVtb, sSt2, cg, p0);

    float acc[8][8];
#pragma unroll
    for (int i=0;i<8;i++)
#pragma unroll
        for (int jp=0;jp<4;jp++)
            unpkf2(acc2[i][jp], acc[i][2*jp], acc[i][2*jp+1]);

    __nv_bfloat16* Ub = ((__nv_bfloat16*)g_dw) + U_OFF;
    size_t ub = ((size_t)b*HWSZ + (size_t)hw00 + (size_t)pg*128)*256 + c0;
#pragma unroll
    for (int j = 0; j < 8; j++) {
        uint4 pkt = make_uint4(pk2(acc[0][j], acc[1][j]), pk2(acc[2][j], acc[3][j]),
                               pk2(acc[4][j], acc[5][j]), pk2(acc[6][j], acc[7][j]));
        *(uint4*)&Ub[ub + (size_t)j*256] = pkt;
    }
}

// ---- K4: bf16 GEMM, cp.async double-buffered fills, 2 CTAs/SM ----
#define GEMM_SMEM_BYTES 69632

__global__ __launch_bounds__(256, 2) void gemm_kernel(
    const float* __restrict__ bvp,
    const float* __restrict__ img, const float* __restrict__ mask,
    const float* __restrict__ alpha_p, const float* __restrict__ beta_p)
{
    extern __shared__ unsigned sg[];
    uint4* sAf = (uint4*)sg;                          // [2][1024]
    __nv_bfloat16* sB = (__nv_bfloat16*)(sg + 8192);  // [2][128*72]
    const __nv_bfloat16* Ub = ((const __nv_bfloat16*)g_dw) + U_OFF;

    const int t = threadIdx.x, lane = t & 31, warp = t >> 5;
    const int warpM = warp >> 2, warpN = warp & 3;
    const int hwt = blockIdx.x, mt = blockIdx.y, b = blockIdx.z;
    const int n0 = hwt * 128;

    unsigned sA_base = (unsigned)__cvta_generic_to_shared(sAf);
    unsigned sB_base = (unsigned)__cvta_generic_to_shared(sB);

    float d[4][4][4];
#pragma unroll
    for (int i=0;i<4;i++)
#pragma unroll
        for (int j=0;j<4;j++)
#pragma unroll
            for (int e=0;e<4;e++) d[i][j][e]=0.f;

    {
#pragma unroll
        for (int s = 0; s < 4; s++) {
            int e = s*256 + t;
            cpa16(sA_base + e*16, &g_wfrag[(mt*4 + 0)*1024 + e]);
        }
#pragma unroll
        for (int s = 0; s < 4; s++) {
            int e = s*256 + t;
            int n = e >> 3, kq = e & 7;
            cpa16(sB_base + (n*72 + kq*8)*2,
                  &Ub[((size_t)b*HWSZ + n0 + n)*256 + kq*8]);
        }
        asm volatile("cp.async.commit_group;" ::: "memory");
    }

    for (int kt = 0; kt < 4; kt++) {
        if (kt < 3) {
            int kn = kt + 1, buf = kn & 1;
            int kc = kn*64;
#pragma unroll
            for (int s = 0; s < 4; s++) {
                int e = s*256 + t;
                cpa16(sA_base + (buf*1024 + e)*16, &g_wfrag[(mt*4 + kn)*1024 + e]);
            }
#pragma unroll
            for (int s = 0; s < 4; s++) {
                int e = s*256 + t;
                int n = e >> 3, kq = e & 7;
                cpa16(sB_base + (buf*9216 + n*72 + kq*8)*2,
                      &Ub[((size_t)b*HWSZ + n0 + n)*256 + kc + kq*8]);
            }
            asm volatile("cp.async.commit_group;" ::: "memory");
            asm volatile("cp.async.wait_group 1;" ::: "memory");
        } else {
            asm volatile("cp.async.wait_group 0;" ::: "memory");
        }
        __syncthreads();

        const uint4* A = sAf + (kt & 1)*1024;
        const __nv_bfloat16* Bs = sB + (kt & 1)*9216;
#pragma unroll
        for (int ks = 0; ks < 4; ks++) {
            int kl = ks*16 + 2*(lane & 3);
            uint4 av[4];
#pragma unroll
            for (int i = 0; i < 4; i++)
                av[i] = A[((ks*2 + warpM)*4 + i)*32 + lane];
            unsigned bb[4][2];
#pragma unroll
            for (int j = 0; j < 4; j++) {
                int n = warpN*32 + j*8 + (lane >> 2);
                bb[j][0] = *(const unsigned*)&Bs[n*72 + kl];
                bb[j][1] = *(const unsigned*)&Bs[n*72 + kl + 8];
            }
#pragma unroll
            for (int i = 0; i < 4; i++) {
                unsigned a[4] = {av[i].x, av[i].y, av[i].z, av[i].w};
#pragma unroll
                for (int j = 0; j < 4; j++) mma_bf16(d[i][j], a, bb[j]);
            }
        }
        __syncthreads();
    }

    float* red = (float*)sg;
    float ab = __ldg(alpha_p) + __ldg(beta_p);
    int r = lane >> 2, cc = (lane & 3)*2;
    int slot = warpN*4 + (lane & 3);
#pragma unroll
    for (int i = 0; i < 4; i++) {
#pragma unroll
        for (int half = 0; half < 2; half++) {
            int ro = warpM*64 + i*16 + r + half*8;
            int o = mt*128 + ro;
            float bias = ab * __ldg(&bvp[o]);
            float s = 0.f, q = 0.f;
#pragma unroll
            for (int j = 0; j < 4; j++) {
                int nl = warpN*32 + j*8 + cc;
                size_t g = ((size_t)(b*256 + o) << 14) + n0 + nl;
                float2 iv = *(const float2*)&img[g];
                float2 mv = *(const float2*)&mask[g];
                float v0 = d[i][j][half*2+0] + bias + iv.x + mv.x;
                float v1 = d[i][j][half*2+1] + bias + iv.y + mv.y;
                *(float2*)&g_fused[g] = make_float2(v0, v1);
                s += v0 + v1; q += v0*v0 + v1*v1;
            }
            red[ro*16 + slot]        = s;
            red[2048 + ro*16 + slot] = q;
        }
    }
    __syncthreads();
    if (t < 128) {
        float s = 0.f, q = 0.f;
#pragma unroll
        for (int k = 0; k < 16; k++) { s += red[t*16+k]; q += red[2048 + t*16+k]; }
        red[4096 + t] = s; red[4224 + t] = q;
    }
    __syncthreads();
    if (t < 16) {
        float s = 0.f, q = 0.f;
#pragma unroll
        for (int k = 0; k < 8; k++) { s += red[4096 + t*8+k]; q += red[4224 + t*8+k]; }
        int g = mt*16 + t;
        int idx = ((b*32 + g)*128 + hwt)*2;
        g_psum[idx] = s; g_psum[idx+1] = q;
    }
}

// ---- K5: reduce GN partials ----
__global__ __launch_bounds__(128) void stats_kernel()
{
    int bg = blockIdx.x, t = threadIdx.x;
    float2 v = ((const float2*)g_psum)[bg*128 + t];
    float s = v.x, q = v.y;
#pragma unroll
    for (int o = 16; o; o >>= 1) {
        s += __shfl_xor_sync(0xffffffffu, s, o);
        q += __shfl_xor_sync(0xffffffffu, q, o);
    }
    __shared__ float ss[4], qs[4];
    if ((t & 31) == 0) { ss[t>>5] = s; qs[t>>5] = q; }
    __syncthreads();
    if (t == 0) {
        for (int w = 1; w < 4; w++) { s += ss[w]; q += qs[w]; }
        float inv = 1.f / 131072.f;
        float mu = s * inv;
        float var = q * inv - mu*mu;
        g_stats[bg] = make_float2(mu, rsqrtf(var + 1e-5f));
    }
}

// ---- K6: normalize ----
__global__ __launch_bounds__(1024) void norm_kernel(
    float* __restrict__ out, const float* __restrict__ gamma, const float* __restrict__ beta)
{
    int i4 = blockIdx.x*1024 + threadIdx.x;
    size_t e = (size_t)i4 << 2;
    int b = (int)(e >> 22), c = (int)(e >> 14) & 255;
    float2 st = g_stats[b*32 + (c >> 3)];
    float gsc = gamma[c] * st.y;
    float bsh = beta[c] - st.x * gsc;
    float4 f = *(const float4*)&g_fused[e];
    float4 r;
    r.x = f.x*gsc + bsh; r.y = f.y*gsc + bsh;
    r.z = f.z*gsc + bsh; r.w = f.w*gsc + bsh;
    *(float4*)&out[e] = r;
}

extern "C" void kernel_launch(void* const* d_in, const int* in_sizes, int n_in,
                              void* d_out, int out_size)
{
    const float* img    = (const float*)d_in[0];
    const float* mask   = (const float*)d_in[1];
    const float* qdw_w  = (const float*)d_in[2];
    const float* qdw_b  = (const float*)d_in[3];
    const float* kdw_w  = (const float*)d_in[4];
    const float* kdw_b  = (const float*)d_in[5];
    const float* vdw_w  = (const float*)d_in[6];
    const float* vdw_b  = (const float*)d_in[7];
    const float* qpw_w  = (const float*)d_in[8];
    const float* qpw_b  = (const float*)d_in[9];
    const float* kpw_w  = (const float*)d_in[10];
    const float* kpw_b  = (const float*)d_in[11];
    const float* vpw_w  = (const float*)d_in[12];
    const float* vpw_b  = (const float*)d_in[13];
    const float* alpha  = (const float*)d_in[14];
    const float* beta   = (const float*)d_in[15];
    const float* gn_w   = (const float*)d_in[16];
    const float* gn_b   = (const float*)d_in[17];

    cudaFuncSetAttribute(attn_kernel, cudaFuncAttributeMaxDynamicSharedMemorySize,
                         ATTN_SMEM_FLOATS * 4);
    cudaFuncSetAttribute(gemm_kernel, cudaFuncAttributeMaxDynamicSharedMemorySize,
                         GEMM_SMEM_BYTES);

    wfrag_kernel<<<32, 256>>>(vpw_w);
    dw_kernel<<<65536, 256>>>(img, mask, qdw_w, qdw_b, kdw_w, kdw_b, vdw_w, vdw_b);
    dim3 g2(256, 4);
    pwqk_kernel<<<g2, 256>>>(qpw_w, qpw_b, kpw_w, kpw_b);
    attn_kernel<<<2048, 256, ATTN_SMEM_FLOATS * 4>>>(alpha, beta);
    dim3 g4(128, 2, 8);
    gemm_kernel<<<g4, 256, GEMM_SMEM_BYTES>>>(vpw_b, img, mask, alpha, beta);
    stats_kernel<<<256, 128>>>();
    norm_kernel<<<8192, 1024>>>((float*)d_out, gn_w, gn_b);
}